// round 2
// baseline (speedup 1.0000x reference)
#include <cuda_runtime.h>
#include <math.h>

// ---------------- problem constants ----------------
#define NTOK 8192       // B*H*W = 8*32*32
#define EMB  768
#define HID  3072       // EMB*4
#define QKVD 2304       // 3*12*64
#define NHEADS_TOT 96   // B * N_HEADS = 8*12
#define SEQ  1024       // H*W
#define HD   64
#define LN_EPS 1e-5f

// ---------------- device scratch (no allocations allowed) ----------------
__device__ float g_ln [NTOK * EMB];                    // 25 MB (LN outputs, reused)
__device__ float g_hid[NTOK * HID];                    // 100 MB (hidden after W1+GELU)
__device__ float g_qkv[NTOK * QKVD];                   // 75 MB
__device__ float g_q  [NHEADS_TOT * SEQ * HD];         // 25 MB
__device__ float g_k  [NHEADS_TOT * SEQ * HD];
__device__ float g_v  [NHEADS_TOT * SEQ * HD];
__device__ float g_sc [(size_t)NHEADS_TOT * SEQ * SEQ];// 402 MB attention scores
__device__ float g_ao [NHEADS_TOT * SEQ * HD];         // 25 MB attn output (b*n, seq, hd)
__device__ float g_x1 [NTOK * EMB];                    // merged attn output
__device__ float g_x2 [NTOK * EMB];                    // proj block output

// ---------------- LayerNorm: one block per token, 256 threads ----------------
__global__ void ln_k(const float* __restrict__ x, const float* __restrict__ g,
                     const float* __restrict__ b, float* __restrict__ y)
{
    const long t = blockIdx.x;
    const float* xr = x + t * EMB;
    float v[3];
    float s = 0.f, s2 = 0.f;
#pragma unroll
    for (int i = 0; i < 3; i++) {
        v[i] = xr[threadIdx.x + i * 256];
        s += v[i];
        s2 += v[i] * v[i];
    }
#pragma unroll
    for (int o = 16; o > 0; o >>= 1) {
        s  += __shfl_xor_sync(0xffffffffu, s,  o);
        s2 += __shfl_xor_sync(0xffffffffu, s2, o);
    }
    __shared__ float rs[8], rs2[8];
    const int w = threadIdx.x >> 5, l = threadIdx.x & 31;
    if (l == 0) { rs[w] = s; rs2[w] = s2; }
    __syncthreads();
    float ts = 0.f, ts2 = 0.f;
#pragma unroll
    for (int i = 0; i < 8; i++) { ts += rs[i]; ts2 += rs2[i]; }
    const float mean = ts * (1.0f / EMB);
    const float var  = ts2 * (1.0f / EMB) - mean * mean;
    const float inv  = rsqrtf(var + LN_EPS);
#pragma unroll
    for (int i = 0; i < 3; i++) {
        const int c = threadIdx.x + i * 256;
        y[t * EMB + c] = (v[i] - mean) * inv * g[c] + b[c];
    }
}

// ---------------- generic tiled GEMM ----------------
// C[R x Mc] = act(op(A) @ op(B) + bias), 64x64 tile, 16x16 threads, 4x4 microtile.
// TA: A accessed transposed (A stored K-major: A^T[r,k] = A[k*lda + r])
// TB: B accessed transposed (B stored [Mc x K] row-major: B^T[k,c] = B[c*ldb + k])
template <bool TA, bool TB, bool DO_GELU, bool DO_BIAS>
__global__ void gemm_k(const float* __restrict__ A, const float* __restrict__ B,
                       const float* __restrict__ bias, float* __restrict__ C,
                       int R, int Mc, int K, int lda, int ldb,
                       long sA, long sB, long sC)
{
    __shared__ float As[16][64];
    __shared__ float Bs[16][64];

    const float* Ab = A + (long)blockIdx.z * sA;
    const float* Bb = B + (long)blockIdx.z * sB;
    float*       Cb = C + (long)blockIdx.z * sC;

    const int r0 = blockIdx.y * 64;
    const int c0 = blockIdx.x * 64;
    const int tid = threadIdx.y * 16 + threadIdx.x;

    float acc[4][4] = {};

    for (int k0 = 0; k0 < K; k0 += 16) {
#pragma unroll
        for (int i = 0; i < 4; i++) {
            const int e = tid + i * 256;
            if (!TA) { const int kk = e & 15, rr = e >> 4;
                       As[kk][rr] = Ab[(long)(r0 + rr) * lda + (k0 + kk)]; }
            else     { const int rr = e & 63, kk = e >> 6;
                       As[kk][rr] = Ab[(long)(k0 + kk) * lda + (r0 + rr)]; }
        }
#pragma unroll
        for (int i = 0; i < 4; i++) {
            const int e = tid + i * 256;
            if (!TB) { const int cc = e & 63, kk = e >> 6;
                       Bs[kk][cc] = Bb[(long)(k0 + kk) * ldb + (c0 + cc)]; }
            else     { const int kk = e & 15, cc = e >> 4;
                       Bs[kk][cc] = Bb[(long)(c0 + cc) * ldb + (k0 + kk)]; }
        }
        __syncthreads();
#pragma unroll
        for (int kt = 0; kt < 16; kt++) {
            float a[4], b[4];
#pragma unroll
            for (int i = 0; i < 4; i++) a[i] = As[kt][threadIdx.y * 4 + i];
#pragma unroll
            for (int j = 0; j < 4; j++) b[j] = Bs[kt][threadIdx.x * 4 + j];
#pragma unroll
            for (int i = 0; i < 4; i++)
#pragma unroll
                for (int j = 0; j < 4; j++)
                    acc[i][j] = fmaf(a[i], b[j], acc[i][j]);
        }
        __syncthreads();
    }

#pragma unroll
    for (int i = 0; i < 4; i++) {
        const int rr = r0 + threadIdx.y * 4 + i;
#pragma unroll
        for (int j = 0; j < 4; j++) {
            const int cc = c0 + threadIdx.x * 4 + j;
            float val = acc[i][j];
            if (DO_BIAS) val += bias[cc];
            if (DO_GELU) val = 0.5f * val * (1.0f + erff(val * 0.70710678118654752f));
            Cb[(long)rr * Mc + cc] = val;
        }
    }
}

// ---------------- split qkv: (tok, (k n s)) -> 3 x (b*n, seq, hd) ----------------
__global__ void split_qkv_k(const float* __restrict__ qkv,
                            float* __restrict__ q, float* __restrict__ k,
                            float* __restrict__ v)
{
    const int idx = blockIdx.x * 256 + threadIdx.x;   // < 8192*2304 = 18.9M
    const int tok = idx / QKVD;
    const int c   = idx - tok * QKVD;
    const int kq  = c / (12 * HD);
    const int rem = c - kq * (12 * HD);
    const int n   = rem >> 6;
    const int s   = rem & 63;
    const int b   = tok >> 10;
    const int p   = tok & 1023;
    const float val = qkv[idx];
    const long dst = (long)(b * 12 + n) * (SEQ * HD) + p * HD + s;
    float* o = (kq == 0) ? q : (kq == 1) ? k : v;
    o[dst] = val;
}

// ---------------- softmax over rows of 1024, with 1/sqrt(64) scale ----------------
__global__ void softmax_k(float* __restrict__ S)
{
    const long row = blockIdx.x;
    float* p = S + row * SEQ;
    float v[4];
    float mx = -1e30f;
#pragma unroll
    for (int i = 0; i < 4; i++) {
        v[i] = p[threadIdx.x + i * 256] * 0.125f;
        mx = fmaxf(mx, v[i]);
    }
#pragma unroll
    for (int o = 16; o > 0; o >>= 1) mx = fmaxf(mx, __shfl_xor_sync(0xffffffffu, mx, o));
    __shared__ float rmax[8], rsum[8];
    const int w = threadIdx.x >> 5, l = threadIdx.x & 31;
    if (l == 0) rmax[w] = mx;
    __syncthreads();
    float m = rmax[0];
#pragma unroll
    for (int i = 1; i < 8; i++) m = fmaxf(m, rmax[i]);

    float s = 0.f;
#pragma unroll
    for (int i = 0; i < 4; i++) { v[i] = __expf(v[i] - m); s += v[i]; }
#pragma unroll
    for (int o = 16; o > 0; o >>= 1) s += __shfl_xor_sync(0xffffffffu, s, o);
    if (l == 0) rsum[w] = s;
    __syncthreads();
    float tot = 0.f;
#pragma unroll
    for (int i = 0; i < 8; i++) tot += rsum[i];
    const float inv = 1.0f / tot;
#pragma unroll
    for (int i = 0; i < 4; i++) p[threadIdx.x + i * 256] = v[i] * inv;
}

// ---------------- merge heads: (b*n, seq, hd) -> (tok, n*hd) ----------------
__global__ void merge_heads_k(const float* __restrict__ ao, float* __restrict__ y)
{
    const int idx = blockIdx.x * 256 + threadIdx.x;   // < 8192*768
    const int tok = idx / EMB;
    const int c   = idx - tok * EMB;
    const int n   = c >> 6;
    const int s   = c & 63;
    const int b   = tok >> 10;
    const int p   = tok & 1023;
    y[idx] = ao[(long)(b * 12 + n) * (SEQ * HD) + p * HD + s];
}

// ---------------- host launcher ----------------
extern "C" void kernel_launch(void* const* d_in, const int* in_sizes, int n_in,
                              void* d_out, int out_size)
{
    const float* x       = (const float*)d_in[0];
    const float* qkv_g   = (const float*)d_in[1];
    const float* qkv_b   = (const float*)d_in[2];
    const float* qkv_W1  = (const float*)d_in[3];
    const float* qkv_b1  = (const float*)d_in[4];
    const float* qkv_W2  = (const float*)d_in[5];
    const float* qkv_b2  = (const float*)d_in[6];
    const float* proj_g  = (const float*)d_in[7];
    const float* proj_b  = (const float*)d_in[8];
    const float* proj_W1 = (const float*)d_in[9];
    const float* proj_b1 = (const float*)d_in[10];
    const float* proj_W2 = (const float*)d_in[11];
    const float* proj_b2 = (const float*)d_in[12];
    const float* mlp_g   = (const float*)d_in[13];
    const float* mlp_b   = (const float*)d_in[14];
    const float* mlp_W1  = (const float*)d_in[15];
    const float* mlp_b1  = (const float*)d_in[16];
    const float* mlp_W2  = (const float*)d_in[17];
    const float* mlp_b2  = (const float*)d_in[18];
    float* out = (float*)d_out;

    float *ln, *hid, *qkv, *q, *k, *v, *sc, *ao, *x1, *x2;
    cudaGetSymbolAddress((void**)&ln,  g_ln);
    cudaGetSymbolAddress((void**)&hid, g_hid);
    cudaGetSymbolAddress((void**)&qkv, g_qkv);
    cudaGetSymbolAddress((void**)&q,   g_q);
    cudaGetSymbolAddress((void**)&k,   g_k);
    cudaGetSymbolAddress((void**)&v,   g_v);
    cudaGetSymbolAddress((void**)&sc,  g_sc);
    cudaGetSymbolAddress((void**)&ao,  g_ao);
    cudaGetSymbolAddress((void**)&x1,  g_x1);
    cudaGetSymbolAddress((void**)&x2,  g_x2);

    const dim3 tb(16, 16);

    // ---- qkv block ----
    ln_k<<<NTOK, 256>>>(x, qkv_g, qkv_b, ln);
    gemm_k<false, false, true,  true><<<dim3(HID / 64, NTOK / 64, 1), tb>>>(
        ln, qkv_W1, qkv_b1, hid, NTOK, HID, EMB, EMB, HID, 0, 0, 0);
    gemm_k<false, false, false, true><<<dim3(QKVD / 64, NTOK / 64, 1), tb>>>(
        hid, qkv_W2, qkv_b2, qkv, NTOK, QKVD, HID, HID, QKVD, 0, 0, 0);

    // ---- attention ----
    split_qkv_k<<<(NTOK * QKVD) / 256, 256>>>(qkv, q, k, v);
    // scores: S[z] = Q[z] @ K[z]^T   (1024 x 1024 x 64), 96 batches
    gemm_k<false, true, false, false><<<dim3(SEQ / 64, SEQ / 64, NHEADS_TOT), tb>>>(
        q, k, nullptr, sc, SEQ, SEQ, HD, HD, HD,
        (long)SEQ * HD, (long)SEQ * HD, (long)SEQ * SEQ);
    softmax_k<<<NHEADS_TOT * SEQ, 256>>>(sc);
    // out: O[z] = P[z]^T @ V[z]      (1024 x 64 x 1024), 96 batches
    gemm_k<true, false, false, false><<<dim3(HD / 64, SEQ / 64, NHEADS_TOT), tb>>>(
        sc, v, nullptr, ao, SEQ, HD, SEQ, SEQ, HD,
        (long)SEQ * SEQ, (long)SEQ * HD, (long)SEQ * HD);
    merge_heads_k<<<(NTOK * EMB) / 256, 256>>>(ao, x1);

    // ---- proj block ----
    ln_k<<<NTOK, 256>>>(x1, proj_g, proj_b, ln);
    gemm_k<false, false, true,  true><<<dim3(HID / 64, NTOK / 64, 1), tb>>>(
        ln, proj_W1, proj_b1, hid, NTOK, HID, EMB, EMB, HID, 0, 0, 0);
    gemm_k<false, false, false, true><<<dim3(EMB / 64, NTOK / 64, 1), tb>>>(
        hid, proj_W2, proj_b2, x2, NTOK, EMB, HID, HID, EMB, 0, 0, 0);

    // ---- mlp block ----
    ln_k<<<NTOK, 256>>>(x2, mlp_g, mlp_b, ln);
    gemm_k<false, false, true,  true><<<dim3(HID / 64, NTOK / 64, 1), tb>>>(
        ln, mlp_W1, mlp_b1, hid, NTOK, HID, EMB, EMB, HID, 0, 0, 0);
    gemm_k<false, false, false, true><<<dim3(EMB / 64, NTOK / 64, 1), tb>>>(
        hid, mlp_W2, mlp_b2, out, NTOK, EMB, HID, HID, EMB, 0, 0, 0);
}

// round 4
// speedup vs baseline: 2.3153x; 2.3153x over previous
#include <cuda_runtime.h>
#include <cuda_bf16.h>
#include <mma.h>
#include <math.h>

using namespace nvcuda;
typedef __nv_bfloat16 bf16;

// ---------------- problem constants ----------------
#define NTOK 8192       // B*H*W = 8*32*32
#define EMB  768
#define HID  3072
#define QKVD 2304       // 3*12*64
#define NBH  96         // B * N_HEADS
#define SEQ  1024
#define HD   64
#define LN_EPS 1e-5f

// ---------------- device scratch (no allocations allowed) ----------------
__device__ bf16  g_lnE [NTOK * 3 * EMB];                 // LN out, expanded A-style
__device__ bf16  g_hidE[(size_t)NTOK * 3 * HID];         // GELU out, expanded A-style (151MB)
__device__ bf16  g_w1E [3 * EMB * HID];                  // expanded W1 (B-style), reused per block
__device__ bf16  g_w2E [(size_t)3 * HID * QKVD];         // expanded W2 (B-style), reused
__device__ float g_qkv [NTOK * QKVD];
__device__ bf16  g_qE  [(size_t)NBH * SEQ * 3 * HD];     // A-style  [bh][t][192]
__device__ bf16  g_kE  [(size_t)NBH * SEQ * 3 * HD];     // B-col    [bh][t][192]
__device__ bf16  g_vE  [(size_t)NBH * 3 * SEQ * HD];     // B-row    [bh][t'][64]
__device__ float g_sc  [(size_t)NBH * SEQ * SEQ];        // scores fp32 (402MB)
__device__ bf16  g_pE  [(size_t)NBH * 3 * SEQ * SEQ];    // softmax expanded (604MB)
__device__ float g_ao  [NBH * SEQ * HD];
__device__ float g_x1  [NTOK * EMB];
__device__ float g_x2  [NTOK * EMB];

__device__ __forceinline__ void split2(float x, bf16& h, bf16& l) {
    h = __float2bfloat16(x);
    l = __float2bfloat16(x - __bfloat162float(h));
}

// ---------------- LayerNorm -> expanded bf16 (A-style: hi, lo, hi) ----------------
__global__ void ln_exp_k(const float* __restrict__ x, const float* __restrict__ g,
                         const float* __restrict__ b, bf16* __restrict__ y)
{
    const long t = blockIdx.x;
    const float* xr = x + t * EMB;
    float v[3];
    float s = 0.f, s2 = 0.f;
#pragma unroll
    for (int i = 0; i < 3; i++) {
        v[i] = xr[threadIdx.x + i * 256];
        s += v[i]; s2 += v[i] * v[i];
    }
#pragma unroll
    for (int o = 16; o > 0; o >>= 1) {
        s  += __shfl_xor_sync(0xffffffffu, s,  o);
        s2 += __shfl_xor_sync(0xffffffffu, s2, o);
    }
    __shared__ float rs[8], rs2[8];
    const int w = threadIdx.x >> 5, l = threadIdx.x & 31;
    if (l == 0) { rs[w] = s; rs2[w] = s2; }
    __syncthreads();
    float ts = 0.f, ts2 = 0.f;
#pragma unroll
    for (int i = 0; i < 8; i++) { ts += rs[i]; ts2 += rs2[i]; }
    const float mean = ts * (1.0f / EMB);
    const float var  = ts2 * (1.0f / EMB) - mean * mean;
    const float inv  = rsqrtf(var + LN_EPS);
    bf16* yr = y + t * (3 * EMB);
#pragma unroll
    for (int i = 0; i < 3; i++) {
        const int c = threadIdx.x + i * 256;
        float val = (v[i] - mean) * inv * g[c] + b[c];
        bf16 h, lo; split2(val, h, lo);
        yr[c] = h; yr[EMB + c] = lo; yr[2 * EMB + c] = h;
    }
}

// ---------------- weight expansion (B-style: hi, hi, lo along K) ----------------
__global__ void wexp_k(const float* __restrict__ W, bf16* __restrict__ We, int K, int N)
{
    const int idx = blockIdx.x * 256 + threadIdx.x;
    if (idx >= K * N) return;
    const int r = idx / N, c = idx - r * N;
    bf16 h, lo; split2(W[idx], h, lo);
    We[(long)r * N + c] = h;
    We[(long)(K + r) * N + c] = h;
    We[(long)(2 * K + r) * N + c] = lo;
}

// ---------------- generic WMMA GEMM: 128 x BN tile, 8 warps ----------------
// AL/BL: 0 = row-major storage, 1 = col-major storage (transposed access)
// EP: 0 = fp32 out, 1 = fp32 out + bias, 2 = bias + GELU + expanded bf16 out (A-style)
template <int BN, int AL, int BL, int EP>
__global__ void __launch_bounds__(256, 2)
gemm_w(const bf16* __restrict__ A, const bf16* __restrict__ B,
       const float* __restrict__ bias, void* __restrict__ Cv,
       int lda, int ldb, int Kexp, int ntot,
       long long sA, long long sB, long long sC)
{
    constexpr int BM  = 128;
    constexpr int WGM = (BN == 128) ? 2 : 4;
    constexpr int WGN = 8 / WGM;
    constexpr int WMt = BM / WGM / 16;       // a-frag tiles per warp
    constexpr int WNt = BN / WGN / 16;       // b-frag tiles per warp
    constexpr int LA  = (AL == 0) ? 40 : 136;
    constexpr int ASZ = (AL == 0) ? BM * LA : 32 * LA;
    constexpr int LB  = (BL == 0) ? BN + 8 : 40;
    constexpr int BSZ = (BL == 0) ? 32 * LB : BN * LB;
    constexpr int LC  = BN + 4;

    extern __shared__ char smraw[];
    bf16*  As = (bf16*)smraw;
    bf16*  Bs = As + ASZ;
    float* Cs = (float*)(Bs + BSZ);

    A += blockIdx.z * sA;
    B += blockIdx.z * sB;

    const int m0 = blockIdx.y * BM, n0 = blockIdx.x * BN;
    const int tid = threadIdx.x;
    const int wid = tid >> 5;
    const int wm = (wid % WGM) * (BM / WGM);
    const int wn = (wid / WGM) * (BN / WGN);

    using ALay = typename std::conditional<AL == 0, wmma::row_major, wmma::col_major>::type;
    using BLay = typename std::conditional<BL == 0, wmma::row_major, wmma::col_major>::type;

    wmma::fragment<wmma::accumulator, 16, 16, 16, float> acc[WMt][WNt];
#pragma unroll
    for (int i = 0; i < WMt; i++)
#pragma unroll
        for (int j = 0; j < WNt; j++)
            wmma::fill_fragment(acc[i][j], 0.0f);

    for (int k0 = 0; k0 < Kexp; k0 += 32) {
        if (AL == 0) {
#pragma unroll
            for (int i = 0; i < (BM * 32 / 8) / 256; i++) {
                const int idx = tid + i * 256;
                const int r = idx >> 2, v = idx & 3;
                *(uint4*)&As[r * LA + v * 8] =
                    *(const uint4*)&A[(long)(m0 + r) * lda + k0 + v * 8];
            }
        } else {
#pragma unroll
            for (int i = 0; i < (32 * BM / 8) / 256; i++) {
                const int idx = tid + i * 256;
                const int r = idx >> 4, v = idx & 15;
                *(uint4*)&As[r * LA + v * 8] =
                    *(const uint4*)&A[(long)(k0 + r) * lda + m0 + v * 8];
            }
        }
        if (BL == 0) {
#pragma unroll
            for (int i = 0; i < (32 * BN / 8) / 256; i++) {
                const int idx = tid + i * 256;
                const int r = idx / (BN / 8), v = idx % (BN / 8);
                *(uint4*)&Bs[r * LB + v * 8] =
                    *(const uint4*)&B[(long)(k0 + r) * ldb + n0 + v * 8];
            }
        } else {
#pragma unroll
            for (int i = 0; i < (BN * 32 / 8) / 256; i++) {
                const int idx = tid + i * 256;
                const int r = idx >> 2, v = idx & 3;
                *(uint4*)&Bs[r * LB + v * 8] =
                    *(const uint4*)&B[(long)(n0 + r) * ldb + k0 + v * 8];
            }
        }
        __syncthreads();

#pragma unroll
        for (int kk = 0; kk < 32; kk += 16) {
            wmma::fragment<wmma::matrix_a, 16, 16, 16, bf16, ALay> af[WMt];
            wmma::fragment<wmma::matrix_b, 16, 16, 16, bf16, BLay> bfr[WNt];
#pragma unroll
            for (int i = 0; i < WMt; i++) {
                const bf16* p = (AL == 0) ? &As[(wm + i * 16) * LA + kk]
                                          : &As[kk * LA + wm + i * 16];
                wmma::load_matrix_sync(af[i], p, LA);
            }
#pragma unroll
            for (int j = 0; j < WNt; j++) {
                const bf16* p = (BL == 0) ? &Bs[kk * LB + wn + j * 16]
                                          : &Bs[(wn + j * 16) * LB + kk];
                wmma::load_matrix_sync(bfr[j], p, LB);
            }
#pragma unroll
            for (int i = 0; i < WMt; i++)
#pragma unroll
                for (int j = 0; j < WNt; j++)
                    wmma::mma_sync(acc[i][j], af[i], bfr[j], acc[i][j]);
        }
        __syncthreads();
    }

    // stage accumulators to shared
#pragma unroll
    for (int i = 0; i < WMt; i++)
#pragma unroll
        for (int j = 0; j < WNt; j++)
            wmma::store_matrix_sync(&Cs[(wm + i * 16) * LC + wn + j * 16],
                                    acc[i][j], LC, wmma::mem_row_major);
    __syncthreads();

    float* Cf = (float*)Cv + blockIdx.z * sC;
    bf16*  Ce = (bf16*)Cv;
#pragma unroll
    for (int i = 0; i < BM * BN / 256; i++) {
        const int e = tid + i * 256;
        const int r = e / BN, c = e % BN;
        float v = Cs[r * LC + c];
        if (EP >= 1) v += bias[n0 + c];
        if (EP == 2) {
            v = 0.5f * v * (1.0f + erff(v * 0.70710678118654752f));
            const long base = (long)(m0 + r) * (3 * (long)ntot) + n0 + c;
            bf16 h, lo; split2(v, h, lo);
            Ce[base] = h; Ce[base + ntot] = lo; Ce[base + 2 * ntot] = h;
        } else {
            Cf[(long)(m0 + r) * ntot + n0 + c] = v;
        }
    }
}

// ---------------- split qkv -> expanded Q (A), K (B-col), V (B-row) ----------------
__global__ void split_qkv_exp_k(const float* __restrict__ qkv,
                                bf16* __restrict__ q, bf16* __restrict__ k,
                                bf16* __restrict__ v)
{
    const int idx = blockIdx.x * 256 + threadIdx.x;
    const int tok = idx / QKVD;
    const int c   = idx - tok * QKVD;
    const int kq  = c / (12 * HD);
    const int rem = c - kq * (12 * HD);
    const int n   = rem >> 6;
    const int s   = rem & 63;
    const int b   = tok >> 10;
    const int p   = tok & 1023;
    const int bh  = b * 12 + n;
    bf16 h, lo; split2(qkv[idx], h, lo);
    if (kq == 0) {
        const long base = (long)bh * (SEQ * 192) + p * 192 + s;
        q[base] = h; q[base + 64] = lo; q[base + 128] = h;       // A-style
    } else if (kq == 1) {
        const long base = (long)bh * (SEQ * 192) + p * 192 + s;
        k[base] = h; k[base + 64] = h; k[base + 128] = lo;       // B-style
    } else {
        const long base = (long)bh * (3 * SEQ * HD) + p * HD + s;
        v[base] = h; v[base + SEQ * HD] = h; v[base + 2 * SEQ * HD] = lo; // B-style
    }
}

// ---------------- softmax -> expanded bf16 P (A-style rows hi, lo, hi) ----------------
__global__ void softmax_exp_k(const float* __restrict__ S, bf16* __restrict__ P)
{
    const long row = blockIdx.x;            // z*SEQ + t
    const int z = (int)(row >> 10), t = (int)(row & 1023);
    const float* p = S + row * SEQ;
    float v[4];
    float mx = -1e30f;
#pragma unroll
    for (int i = 0; i < 4; i++) {
        v[i] = p[threadIdx.x + i * 256] * 0.125f;
        mx = fmaxf(mx, v[i]);
    }
#pragma unroll
    for (int o = 16; o > 0; o >>= 1) mx = fmaxf(mx, __shfl_xor_sync(0xffffffffu, mx, o));
    __shared__ float rmax[8], rsum[8];
    const int w = threadIdx.x >> 5, l = threadIdx.x & 31;
    if (l == 0) rmax[w] = mx;
    __syncthreads();
    float m = rmax[0];
#pragma unroll
    for (int i = 1; i < 8; i++) m = fmaxf(m, rmax[i]);
    float s = 0.f;
#pragma unroll
    for (int i = 0; i < 4; i++) { v[i] = __expf(v[i] - m); s += v[i]; }
#pragma unroll
    for (int o = 16; o > 0; o >>= 1) s += __shfl_xor_sync(0xffffffffu, s, o);
    if (l == 0) rsum[w] = s;
    __syncthreads();
    float tot = 0.f;
#pragma unroll
    for (int i = 0; i < 8; i++) tot += rsum[i];
    const float inv = 1.0f / tot;
    bf16* out = P + (long)z * (3 * SEQ * SEQ) + (long)t * SEQ;
#pragma unroll
    for (int i = 0; i < 4; i++) {
        const int c = threadIdx.x + i * 256;
        bf16 h, lo; split2(v[i] * inv, h, lo);
        out[c] = h;
        out[c + SEQ * SEQ] = lo;
        out[c + 2 * SEQ * SEQ] = h;
    }
}

// ---------------- merge heads: (b*n, seq, hd) -> (tok, n*hd) ----------------
__global__ void merge_heads_k(const float* __restrict__ ao, float* __restrict__ y)
{
    const int idx = blockIdx.x * 256 + threadIdx.x;
    const int tok = idx / EMB;
    const int c   = idx - tok * EMB;
    const int n   = c >> 6;
    const int s   = c & 63;
    const int b   = tok >> 10;
    const int p   = tok & 1023;
    y[idx] = ao[(long)(b * 12 + n) * (SEQ * HD) + p * HD + s];
}

// ---------------- host launcher ----------------
// dynamic smem sizes per instantiation
#define SM_RR  ((5120 + 4352) * 2 + 128 * 132 * 4)   // 86528  (A row 128x40, B row 32x136, C 128x132)
#define SM_RC  ((5120 + 5120) * 2 + 128 * 132 * 4)   // 88064  (B col 128x40)
#define SM_PV  ((4352 + 2304) * 2 + 128 * 68 * 4)    // 48128  (A col 32x136, B row 32x72, C 128x68)

extern "C" void kernel_launch(void* const* d_in, const int* in_sizes, int n_in,
                              void* d_out, int out_size)
{
    const float* x       = (const float*)d_in[0];
    const float* qkv_g   = (const float*)d_in[1];
    const float* qkv_b   = (const float*)d_in[2];
    const float* qkv_W1  = (const float*)d_in[3];
    const float* qkv_b1  = (const float*)d_in[4];
    const float* qkv_W2  = (const float*)d_in[5];
    const float* qkv_b2  = (const float*)d_in[6];
    const float* proj_g  = (const float*)d_in[7];
    const float* proj_b  = (const float*)d_in[8];
    const float* proj_W1 = (const float*)d_in[9];
    const float* proj_b1 = (const float*)d_in[10];
    const float* proj_W2 = (const float*)d_in[11];
    const float* proj_b2 = (const float*)d_in[12];
    const float* mlp_g   = (const float*)d_in[13];
    const float* mlp_b   = (const float*)d_in[14];
    const float* mlp_W1  = (const float*)d_in[15];
    const float* mlp_b1  = (const float*)d_in[16];
    const float* mlp_W2  = (const float*)d_in[17];
    const float* mlp_b2  = (const float*)d_in[18];
    float* out = (float*)d_out;

    bf16 *lnE, *hidE, *w1E, *w2E, *qE, *kE, *vE, *pE;
    float *qkv, *sc, *ao, *x1, *x2;
    cudaGetSymbolAddress((void**)&lnE,  g_lnE);
    cudaGetSymbolAddress((void**)&hidE, g_hidE);
    cudaGetSymbolAddress((void**)&w1E,  g_w1E);
    cudaGetSymbolAddress((void**)&w2E,  g_w2E);
    cudaGetSymbolAddress((void**)&qkv,  g_qkv);
    cudaGetSymbolAddress((void**)&qE,   g_qE);
    cudaGetSymbolAddress((void**)&kE,   g_kE);
    cudaGetSymbolAddress((void**)&vE,   g_vE);
    cudaGetSymbolAddress((void**)&sc,   g_sc);
    cudaGetSymbolAddress((void**)&pE,   g_pE);
    cudaGetSymbolAddress((void**)&ao,   g_ao);
    cudaGetSymbolAddress((void**)&x1,   g_x1);
    cudaGetSymbolAddress((void**)&x2,   g_x2);

    cudaFuncSetAttribute(gemm_w<128,0,0,2>, cudaFuncAttributeMaxDynamicSharedMemorySize, SM_RR);
    cudaFuncSetAttribute(gemm_w<128,0,0,1>, cudaFuncAttributeMaxDynamicSharedMemorySize, SM_RR);
    cudaFuncSetAttribute(gemm_w<128,0,1,0>, cudaFuncAttributeMaxDynamicSharedMemorySize, SM_RC);
    cudaFuncSetAttribute(gemm_w<64,1,0,0>,  cudaFuncAttributeMaxDynamicSharedMemorySize, SM_PV);

    // ======== qkv block ========
    ln_exp_k<<<NTOK, 256>>>(x, qkv_g, qkv_b, lnE);
    wexp_k<<<(EMB * HID + 255) / 256, 256>>>(qkv_W1, w1E, EMB, HID);
    gemm_w<128,0,0,2><<<dim3(HID / 128, NTOK / 128, 1), 256, SM_RR>>>(
        lnE, w1E, qkv_b1, hidE, 3 * EMB, HID, 3 * EMB, HID, 0, 0, 0);
    wexp_k<<<(HID * QKVD + 255) / 256, 256>>>(qkv_W2, w2E, HID, QKVD);
    gemm_w<128,0,0,1><<<dim3(QKVD / 128, NTOK / 128, 1), 256, SM_RR>>>(
        hidE, w2E, qkv_b2, qkv, 3 * HID, QKVD, 3 * HID, QKVD, 0, 0, 0);

    // ======== attention ========
    split_qkv_exp_k<<<(NTOK * QKVD) / 256, 256>>>(qkv, qE, kE, vE);
    // scores: S[z] = Qe[z] @ Ke[z]^T   (1024 x 1024, Kexp=192), 96 heads
    gemm_w<128,0,1,0><<<dim3(SEQ / 128, SEQ / 128, NBH), 256, SM_RC>>>(
        qE, kE, nullptr, sc, 192, 192, 192, SEQ,
        (long long)SEQ * 192, (long long)SEQ * 192, (long long)SEQ * SEQ);
    softmax_exp_k<<<NBH * SEQ, 256>>>(sc, pE);
    // O[z] = Pe[z]^T-access (col-major) @ Ve[z]   (1024 x 64, Kexp=3072), 96 heads
    gemm_w<64,1,0,0><<<dim3(1, SEQ / 128, NBH), 256, SM_PV>>>(
        pE, vE, nullptr, ao, SEQ, HD, 3 * SEQ, HD,
        (long long)3 * SEQ * SEQ, (long long)3 * SEQ * HD, (long long)SEQ * HD);
    merge_heads_k<<<(NTOK * EMB) / 256, 256>>>(ao, x1);

    // ======== proj block ========
    ln_exp_k<<<NTOK, 256>>>(x1, proj_g, proj_b, lnE);
    wexp_k<<<(EMB * HID + 255) / 256, 256>>>(proj_W1, w1E, EMB, HID);
    gemm_w<128,0,0,2><<<dim3(HID / 128, NTOK / 128, 1), 256, SM_RR>>>(
        lnE, w1E, proj_b1, hidE, 3 * EMB, HID, 3 * EMB, HID, 0, 0, 0);
    wexp_k<<<(HID * EMB + 255) / 256, 256>>>(proj_W2, w2E, HID, EMB);
    gemm_w<128,0,0,1><<<dim3(EMB / 128, NTOK / 128, 1), 256, SM_RR>>>(
        hidE, w2E, proj_b2, x2, 3 * HID, EMB, 3 * HID, EMB, 0, 0, 0);

    // ======== mlp block ========
    ln_exp_k<<<NTOK, 256>>>(x2, mlp_g, mlp_b, lnE);
    wexp_k<<<(EMB * HID + 255) / 256, 256>>>(mlp_W1, w1E, EMB, HID);
    gemm_w<128,0,0,2><<<dim3(HID / 128, NTOK / 128, 1), 256, SM_RR>>>(
        lnE, w1E, mlp_b1, hidE, 3 * EMB, HID, 3 * EMB, HID, 0, 0, 0);
    wexp_k<<<(HID * EMB + 255) / 256, 256>>>(mlp_W2, w2E, HID, EMB);
    gemm_w<128,0,0,1><<<dim3(EMB / 128, NTOK / 128, 1), 256, SM_RR>>>(
        hidE, w2E, mlp_b2, out, 3 * HID, EMB, 3 * HID, EMB, 0, 0, 0);
}

// round 8
// speedup vs baseline: 2.6338x; 1.1376x over previous
#include <cuda_runtime.h>
#include <cuda_bf16.h>
#include <mma.h>
#include <math.h>
#include <cstdint>

using namespace nvcuda;
typedef __nv_bfloat16 bf16;

// ---------------- problem constants ----------------
#define NTOK 8192
#define EMB  768
#define HID  3072
#define QKVD 2304
#define NBH  96
#define SEQ  1024
#define HD   64
#define LN_EPS 1e-5f

// ---------------- device scratch ----------------
__device__ bf16  g_lnE [NTOK * 3 * EMB];
__device__ bf16  g_hidE[(size_t)NTOK * 3 * HID];
__device__ bf16  g_w1E [3 * EMB * HID];                  // expanded [3K, N] row-major
__device__ bf16  g_w2E [(size_t)3 * HID * QKVD];         // expanded [3K, N] row-major
__device__ float g_qkv [NTOK * QKVD];
__device__ bf16  g_qE  [(size_t)NBH * SEQ * 3 * HD];
__device__ bf16  g_kE  [(size_t)NBH * SEQ * 3 * HD];
__device__ bf16  g_vE  [(size_t)NBH * 3 * SEQ * HD];
__device__ float g_sc  [(size_t)NBH * SEQ * SEQ];
__device__ bf16  g_pE  [(size_t)NBH * 3 * SEQ * SEQ];
__device__ float g_ao  [NBH * SEQ * HD];
__device__ float g_x1  [NTOK * EMB];
__device__ float g_x2  [NTOK * EMB];

__device__ __forceinline__ void split2(float x, bf16& h, bf16& l) {
    h = __float2bfloat16(x);
    l = __float2bfloat16(x - __bfloat162float(h));
}

// ---------------- cp.async helpers ----------------
__device__ __forceinline__ uint32_t smem_u32(const void* p) {
    uint32_t a;
    asm("{ .reg .u64 t; cvta.to.shared.u64 t, %1; cvt.u32.u64 %0, t; }" : "=r"(a) : "l"(p));
    return a;
}
__device__ __forceinline__ void cpa16(uint32_t dst, const void* src) {
    asm volatile("cp.async.cg.shared.global [%0], [%1], 16;" :: "r"(dst), "l"(src));
}
#define CP_COMMIT() asm volatile("cp.async.commit_group;" ::: "memory")
#define CP_WAIT1()  asm volatile("cp.async.wait_group 1;" ::: "memory")

// ================= pipelined WMMA GEMM =================
// C[BM=128 x BN tile] = act(op(A) @ op(B) + bias)
// AL: 0 A row-major [M,K]; 1 A col-major [K,M]
// BL: 0 B row-major [K,N]; 1 B col-major [N,K]
// EP: 0 fp32 out, 1 fp32+bias, 2 bias+GELU+expanded bf16 (hi,lo,hi segments)
template <int BN, int AL, int BL, int EP>
__global__ void __launch_bounds__(256, 2)
gemm_p(const bf16* __restrict__ A, const bf16* __restrict__ B,
       const float* __restrict__ bias, void* __restrict__ Cv,
       int lda, int ldb, int Kexp, int ntot,
       long long sA, long long sB, long long sC)
{
    constexpr int BM  = 128;
    constexpr int WGM = (BN == 128) ? 2 : 4;
    constexpr int WGN = 8 / WGM;
    constexpr int WMt = BM / WGM / 16;
    constexpr int WNt = BN / WGN / 16;
    constexpr int LA   = (AL == 0) ? 40 : 136;
    constexpr int ASTG = (AL == 0) ? BM * LA : 32 * LA;     // elems / stage
    constexpr int LB   = (BL == 0) ? BN + 8 : 40;
    constexpr int BSTG = (BL == 0) ? 32 * LB : BN * LB;
    constexpr int STG  = ASTG + BSTG;
    constexpr int LC   = BN + 4;
    constexpr int AOPS = 512;                               // 16B chunks per stage
    constexpr int BOPS = (BL == 0) ? 32 * (BN / 8) : BN * 4;

    extern __shared__ char smraw[];
    const uint32_t smb = smem_u32(smraw);
    const int tid = threadIdx.x, wid = tid >> 5;

    A += blockIdx.z * sA;
    B += blockIdx.z * sB;
    const int m0 = blockIdx.y * BM, n0 = blockIdx.x * BN;
    const int nk = Kexp >> 5;

    auto FILL = [&](int kc, int s) {
        const uint32_t ab = smb + s * (STG * 2);
        const uint32_t bb = ab + ASTG * 2;
        const int k0 = kc * 32;
#pragma unroll
        for (int i = 0; i < AOPS / 256; i++) {
            const int e = tid + i * 256;
            if (AL == 0) {
                const int r = e >> 2, v = e & 3;
                cpa16(ab + (r * LA + v * 8) * 2,
                      A + (long long)(m0 + r) * lda + k0 + v * 8);
            } else {
                const int r = e >> 4, v = e & 15;
                cpa16(ab + (r * LA + v * 8) * 2,
                      A + (long long)(k0 + r) * lda + m0 + v * 8);
            }
        }
#pragma unroll
        for (int i = 0; i < BOPS / 256; i++) {
            const int e = tid + i * 256;
            if (BL == 0) {
                const int r = e / (BN / 8), v = e % (BN / 8);
                cpa16(bb + (r * LB + v * 8) * 2,
                      B + (long long)(k0 + r) * ldb + n0 + v * 8);
            } else {
                const int r = e >> 2, v = e & 3;
                cpa16(bb + (r * LB + v * 8) * 2,
                      B + (long long)(n0 + r) * ldb + k0 + v * 8);
            }
        }
    };

    const int wm = (wid % WGM) * (BM / WGM);
    const int wn = (wid / WGM) * (BN / WGN);

    using ALay = typename std::conditional<AL == 0, wmma::row_major, wmma::col_major>::type;
    using BLay = typename std::conditional<BL == 0, wmma::row_major, wmma::col_major>::type;

    wmma::fragment<wmma::accumulator, 16, 16, 16, float> acc[WMt][WNt];
#pragma unroll
    for (int i = 0; i < WMt; i++)
#pragma unroll
        for (int j = 0; j < WNt; j++)
            wmma::fill_fragment(acc[i][j], 0.0f);

    // prologue: stages 0 and 1 in flight
    FILL(0, 0); CP_COMMIT();
    FILL(1, 1); CP_COMMIT();

    for (int kc = 0; kc < nk; kc++) {
        const int s = kc % 3;
        CP_WAIT1();
        __syncthreads();
        // issue next-next stage fill BEFORE compute so DMA overlaps MMA
        if (kc + 2 < nk) FILL(kc + 2, (kc + 2) % 3);
        CP_COMMIT();

        bf16* As = (bf16*)smraw + s * STG;
        bf16* Bs = As + ASTG;
#pragma unroll
        for (int kk = 0; kk < 32; kk += 16) {
            wmma::fragment<wmma::matrix_a, 16, 16, 16, bf16, ALay> af[WMt];
            wmma::fragment<wmma::matrix_b, 16, 16, 16, bf16, BLay> bfr[WNt];
#pragma unroll
            for (int i = 0; i < WMt; i++) {
                const bf16* p = (AL == 0) ? &As[(wm + i * 16) * LA + kk]
                                          : &As[kk * LA + wm + i * 16];
                wmma::load_matrix_sync(af[i], p, LA);
            }
#pragma unroll
            for (int j = 0; j < WNt; j++) {
                const bf16* p = (BL == 0) ? &Bs[kk * LB + wn + j * 16]
                                          : &Bs[(wn + j * 16) * LB + kk];
                wmma::load_matrix_sync(bfr[j], p, LB);
            }
#pragma unroll
            for (int i = 0; i < WMt; i++)
#pragma unroll
                for (int j = 0; j < WNt; j++)
                    wmma::mma_sync(acc[i][j], af[i], bfr[j], acc[i][j]);
        }
    }
    __syncthreads();

    // stage accumulators to shared, then fused epilogue
    float* Cs = (float*)smraw;
#pragma unroll
    for (int i = 0; i < WMt; i++)
#pragma unroll
        for (int j = 0; j < WNt; j++)
            wmma::store_matrix_sync(&Cs[(wm + i * 16) * LC + wn + j * 16],
                                    acc[i][j], LC, wmma::mem_row_major);
    __syncthreads();

    float* Cf = (float*)Cv + blockIdx.z * sC;
    bf16*  Ce = (bf16*)Cv;
#pragma unroll
    for (int i = 0; i < BM * BN / 256; i++) {
        const int e = tid + i * 256;
        const int r = e / BN, c = e % BN;
        float v = Cs[r * LC + c];
        if (EP >= 1) v += bias[n0 + c];
        if (EP == 2) {
            v = 0.5f * v * (1.0f + erff(v * 0.70710678118654752f));
            const long long base = (long long)(m0 + r) * (3LL * ntot) + n0 + c;
            bf16 h, lo; split2(v, h, lo);
            Ce[base] = h; Ce[base + ntot] = lo; Ce[base + 2 * ntot] = h;
        } else {
            Cf[(long long)(m0 + r) * ntot + n0 + c] = v;
        }
    }
}

// ---------------- LayerNorm -> expanded bf16 (A-style: hi, lo, hi) ----------------
__global__ void ln_exp_k(const float* __restrict__ x, const float* __restrict__ g,
                         const float* __restrict__ b, bf16* __restrict__ y)
{
    const long t = blockIdx.x;
    const float* xr = x + t * EMB;
    float v[3];
    float s = 0.f, s2 = 0.f;
#pragma unroll
    for (int i = 0; i < 3; i++) {
        v[i] = xr[threadIdx.x + i * 256];
        s += v[i]; s2 += v[i] * v[i];
    }
#pragma unroll
    for (int o = 16; o > 0; o >>= 1) {
        s  += __shfl_xor_sync(0xffffffffu, s,  o);
        s2 += __shfl_xor_sync(0xffffffffu, s2, o);
    }
    __shared__ float rs[8], rs2[8];
    const int w = threadIdx.x >> 5, l = threadIdx.x & 31;
    if (l == 0) { rs[w] = s; rs2[w] = s2; }
    __syncthreads();
    float ts = 0.f, ts2 = 0.f;
#pragma unroll
    for (int i = 0; i < 8; i++) { ts += rs[i]; ts2 += rs2[i]; }
    const float mean = ts * (1.0f / EMB);
    const float var  = ts2 * (1.0f / EMB) - mean * mean;
    const float inv  = rsqrtf(var + LN_EPS);
    bf16* yr = y + t * (3 * EMB);
#pragma unroll
    for (int i = 0; i < 3; i++) {
        const int c = threadIdx.x + i * 256;
        float val = (v[i] - mean) * inv * g[c] + b[c];
        bf16 h, lo; split2(val, h, lo);
        yr[c] = h; yr[EMB + c] = lo; yr[2 * EMB + c] = h;
    }
}

// ------- weight expansion (B-style: hi, hi, lo along K), [3K, N] row-major -------
__global__ void wexp_k(const float* __restrict__ W, bf16* __restrict__ We, int K, int N)
{
    const int idx = blockIdx.x * 256 + threadIdx.x;
    if (idx >= K * N) return;
    const int r = idx / N, c = idx - r * N;
    bf16 h, lo; split2(W[idx], h, lo);
    We[(long)r * N + c] = h;
    We[(long)(K + r) * N + c] = h;
    We[(long)(2 * K + r) * N + c] = lo;
}

// ---------------- split qkv -> expanded Q (A), K (B-col), V (B-row) ----------------
__global__ void split_qkv_exp_k(const float* __restrict__ qkv,
                                bf16* __restrict__ q, bf16* __restrict__ k,
                                bf16* __restrict__ v)
{
    const int idx = blockIdx.x * 256 + threadIdx.x;
    const int tok = idx / QKVD;
    const int c   = idx - tok * QKVD;
    const int kq  = c / (12 * HD);
    const int rem = c - kq * (12 * HD);
    const int n   = rem >> 6;
    const int s   = rem & 63;
    const int b   = tok >> 10;
    const int p   = tok & 1023;
    const int bh  = b * 12 + n;
    bf16 h, lo; split2(qkv[idx], h, lo);
    if (kq == 0) {
        const long base = (long)bh * (SEQ * 192) + p * 192 + s;
        q[base] = h; q[base + 64] = lo; q[base + 128] = h;
    } else if (kq == 1) {
        const long base = (long)bh * (SEQ * 192) + p * 192 + s;
        k[base] = h; k[base + 64] = h; k[base + 128] = lo;
    } else {
        const long base = (long)bh * (3 * SEQ * HD) + p * HD + s;
        v[base] = h; v[base + SEQ * HD] = h; v[base + 2 * SEQ * HD] = lo;
    }
}

// ---------------- softmax -> expanded bf16 P ----------------
__global__ void softmax_exp_k(const float* __restrict__ S, bf16* __restrict__ P)
{
    const long row = blockIdx.x;
    const int z = (int)(row >> 10), t = (int)(row & 1023);
    const float* p = S + row * SEQ;
    float v[4];
    float mx = -1e30f;
#pragma unroll
    for (int i = 0; i < 4; i++) {
        v[i] = p[threadIdx.x + i * 256] * 0.125f;
        mx = fmaxf(mx, v[i]);
    }
#pragma unroll
    for (int o = 16; o > 0; o >>= 1) mx = fmaxf(mx, __shfl_xor_sync(0xffffffffu, mx, o));
    __shared__ float rmax[8], rsum[8];
    const int w = threadIdx.x >> 5, l = threadIdx.x & 31;
    if (l == 0) rmax[w] = mx;
    __syncthreads();
    float m = rmax[0];
#pragma unroll
    for (int i = 1; i < 8; i++) m = fmaxf(m, rmax[i]);
    float s = 0.f;
#pragma unroll
    for (int i = 0; i < 4; i++) { v[i] = __expf(v[i] - m); s += v[i]; }
#pragma unroll
    for (int o = 16; o > 0; o >>= 1) s += __shfl_xor_sync(0xffffffffu, s, o);
    if (l == 0) rsum[w] = s;
    __syncthreads();
    float tot = 0.f;
#pragma unroll
    for (int i = 0; i < 8; i++) tot += rsum[i];
    const float inv = 1.0f / tot;
    bf16* out = P + (long)z * (3 * SEQ * SEQ) + (long)t * SEQ;
#pragma unroll
    for (int i = 0; i < 4; i++) {
        const int c = threadIdx.x + i * 256;
        bf16 h, lo; split2(v[i] * inv, h, lo);
        out[c] = h;
        out[c + SEQ * SEQ] = lo;
        out[c + 2 * SEQ * SEQ] = h;
    }
}

// ---------------- merge heads ----------------
__global__ void merge_heads_k(const float* __restrict__ ao, float* __restrict__ y)
{
    const int idx = blockIdx.x * 256 + threadIdx.x;
    const int tok = idx / EMB;
    const int c   = idx - tok * EMB;
    const int n   = c >> 6;
    const int s   = c & 63;
    const int b   = tok >> 10;
    const int p   = tok & 1023;
    y[idx] = ao[(long)(b * 12 + n) * (SEQ * HD) + p * HD + s];
}

// ---------------- host launcher ----------------
// dynamic smem per instantiation: max(3 * stage_bytes, C staging bytes)
#define SM_RR 67584   // stage=(128*40+32*136)*2=18944, 3x=56832; Cs=128*132*4=67584
#define SM_RC 67584   // stage=(128*40+128*40)*2=20480, 3x=61440; Cs=67584
#define SM_PV 39936   // stage=(32*136+32*72)*2=13312, 3x=39936; Cs=128*68*4=34816

extern "C" void kernel_launch(void* const* d_in, const int* in_sizes, int n_in,
                              void* d_out, int out_size)
{
    const float* x       = (const float*)d_in[0];
    const float* qkv_g   = (const float*)d_in[1];
    const float* qkv_b   = (const float*)d_in[2];
    const float* qkv_W1  = (const float*)d_in[3];
    const float* qkv_b1  = (const float*)d_in[4];
    const float* qkv_W2  = (const float*)d_in[5];
    const float* qkv_b2  = (const float*)d_in[6];
    const float* proj_g  = (const float*)d_in[7];
    const float* proj_b  = (const float*)d_in[8];
    const float* proj_W1 = (const float*)d_in[9];
    const float* proj_b1 = (const float*)d_in[10];
    const float* proj_W2 = (const float*)d_in[11];
    const float* proj_b2 = (const float*)d_in[12];
    const float* mlp_g   = (const float*)d_in[13];
    const float* mlp_b   = (const float*)d_in[14];
    const float* mlp_W1  = (const float*)d_in[15];
    const float* mlp_b1  = (const float*)d_in[16];
    const float* mlp_W2  = (const float*)d_in[17];
    const float* mlp_b2  = (const float*)d_in[18];
    float* out = (float*)d_out;

    bf16 *lnE, *hidE, *w1E, *w2E, *qE, *kE, *vE, *pE;
    float *qkv, *sc, *ao, *x1, *x2;
    cudaGetSymbolAddress((void**)&lnE,  g_lnE);
    cudaGetSymbolAddress((void**)&hidE, g_hidE);
    cudaGetSymbolAddress((void**)&w1E,  g_w1E);
    cudaGetSymbolAddress((void**)&w2E,  g_w2E);
    cudaGetSymbolAddress((void**)&qkv,  g_qkv);
    cudaGetSymbolAddress((void**)&qE,   g_qE);
    cudaGetSymbolAddress((void**)&kE,   g_kE);
    cudaGetSymbolAddress((void**)&vE,   g_vE);
    cudaGetSymbolAddress((void**)&sc,   g_sc);
    cudaGetSymbolAddress((void**)&pE,   g_pE);
    cudaGetSymbolAddress((void**)&ao,   g_ao);
    cudaGetSymbolAddress((void**)&x1,   g_x1);
    cudaGetSymbolAddress((void**)&x2,   g_x2);

    cudaFuncSetAttribute(gemm_p<128,0,0,2>, cudaFuncAttributeMaxDynamicSharedMemorySize, SM_RR);
    cudaFuncSetAttribute(gemm_p<128,0,0,1>, cudaFuncAttributeMaxDynamicSharedMemorySize, SM_RR);
    cudaFuncSetAttribute(gemm_p<128,0,1,0>, cudaFuncAttributeMaxDynamicSharedMemorySize, SM_RC);
    cudaFuncSetAttribute(gemm_p<64,1,0,0>,  cudaFuncAttributeMaxDynamicSharedMemorySize, SM_PV);

    // ======== qkv block ========
    ln_exp_k<<<NTOK, 256>>>(x, qkv_g, qkv_b, lnE);
    wexp_k<<<(EMB * HID + 255) / 256, 256>>>(qkv_W1, w1E, EMB, HID);
    gemm_p<128,0,0,2><<<dim3(HID / 128, NTOK / 128, 1), 256, SM_RR>>>(
        lnE, w1E, qkv_b1, hidE, 3 * EMB, HID, 3 * EMB, HID, 0, 0, 0);
    wexp_k<<<(HID * QKVD + 255) / 256, 256>>>(qkv_W2, w2E, HID, QKVD);
    gemm_p<128,0,0,1><<<dim3(QKVD / 128, NTOK / 128, 1), 256, SM_RR>>>(
        hidE, w2E, qkv_b2, qkv, 3 * HID, QKVD, 3 * HID, QKVD, 0, 0, 0);

    // ======== attention ========
    split_qkv_exp_k<<<(NTOK * QKVD) / 256, 256>>>(qkv, qE, kE, vE);
    gemm_p<128,0,1,0><<<dim3(SEQ / 128, SEQ / 128, NBH), 256, SM_RC>>>(
        qE, kE, nullptr, sc, 192, 192, 192, SEQ,
        (long long)SEQ * 192, (long long)SEQ * 192, (long long)SEQ * SEQ);
    softmax_exp_k<<<NBH * SEQ, 256>>>(sc, pE);
    gemm_p<64,1,0,0><<<dim3(1, SEQ / 128, NBH), 256, SM_PV>>>(
        pE, vE, nullptr, ao, SEQ, HD, 3 * SEQ, HD,
        (long long)3 * SEQ * SEQ, (long long)3 * SEQ * HD, (long long)SEQ * HD);
    merge_heads_k<<<(NTOK * EMB) / 256, 256>>>(ao, x1);

    // ======== proj block ========
    ln_exp_k<<<NTOK, 256>>>(x1, proj_g, proj_b, lnE);
    wexp_k<<<(EMB * HID + 255) / 256, 256>>>(proj_W1, w1E, EMB, HID);
    gemm_p<128,0,0,2><<<dim3(HID / 128, NTOK / 128, 1), 256, SM_RR>>>(
        lnE, w1E, proj_b1, hidE, 3 * EMB, HID, 3 * EMB, HID, 0, 0, 0);
    wexp_k<<<(HID * EMB + 255) / 256, 256>>>(proj_W2, w2E, HID, EMB);
    gemm_p<128,0,0,1><<<dim3(EMB / 128, NTOK / 128, 1), 256, SM_RR>>>(
        hidE, w2E, proj_b2, x2, 3 * HID, EMB, 3 * HID, EMB, 0, 0, 0);

    // ======== mlp block ========
    ln_exp_k<<<NTOK, 256>>>(x2, mlp_g, mlp_b, lnE);
    wexp_k<<<(EMB * HID + 255) / 256, 256>>>(mlp_W1, w1E, EMB, HID);
    gemm_p<128,0,0,2><<<dim3(HID / 128, NTOK / 128, 1), 256, SM_RR>>>(
        lnE, w1E, mlp_b1, hidE, 3 * EMB, HID, 3 * EMB, HID, 0, 0, 0);
    wexp_k<<<(HID * EMB + 255) / 256, 256>>>(mlp_W2, w2E, HID, EMB);
    gemm_p<128,0,0,1><<<dim3(EMB / 128, NTOK / 128, 1), 256, SM_RR>>>(
        hidE, w2E, mlp_b2, out, 3 * HID, EMB, 3 * HID, EMB, 0, 0, 0);
}